// round 9
// baseline (speedup 1.0000x reference)
#include <cuda_runtime.h>
#include <cuda_fp16.h>
#include <math.h>
#include <stdint.h>

#define FT 256
#define NC 16
#define NMAX 100000
#define G2 592            // 4 blocks/SM * 148 SMs
#define TILE_ROWS 16
#define MTILE 128

typedef unsigned long long ull;

// -------- device scratch (static; no allocation allowed) --------
__device__ __half g_rawH[(size_t)(NMAX + MTILE) * FT];  // row-major fp16 (+pad rows stay zero)
__device__ float  g_rnorm[NMAX];
__device__ float  g_partial[(size_t)G2 * NC * FT];      // per-block class partials
__device__ int    g_pcnt[G2 * NC];                      // per-block class counts
__device__ __half g_aveH[NC * FT];                      // pre-swizzled B image (8KB)
__device__ float  g_avenorm[NC];

__device__ __forceinline__ float eluf(float x) {
    return x > 0.f ? x : (__expf(x) - 1.f);
}
__device__ __forceinline__ ull pack2(float x, float y) {
    ull r; asm("mov.b64 %0,{%1,%2};" : "=l"(r) : "f"(x), "f"(y)); return r;
}
__device__ __forceinline__ uint32_t smem_u32(const void* p) {
    uint32_t a;
    asm("{ .reg .u64 t; cvta.to.shared.u64 t, %1; cvt.u32.u64 %0, t; }" : "=r"(a) : "l"(p));
    return a;
}

// ============ kernel 1: pointwise + fp16 store + class partials + histogram ============
__global__ void __launch_bounds__(256, 4)
k_main(const float4* __restrict__ seq4, const float4* __restrict__ seq14,
       const int* __restrict__ labels,
       const float4* __restrict__ p14, const float4* __restrict__ p24,
       const float4* __restrict__ p34, const float* __restrict__ wwp,
       const float* __restrict__ wwf, const float4* __restrict__ wdp4,
       const float* __restrict__ a4p, int N, int ntiles) {
    extern __shared__ char smraw[];
    __half2* s_tile = (__half2*)smraw;                 // [16][128] = 8KB
    ull*     s_acc  = (ull*)(smraw + 8192);            // [2][16][128] = 32KB
    int*     s_lab  = (int*)(smraw + 8192 + 32768);    // 16 ints
    int*     s_cnt  = (int*)(smraw + 8192 + 32768 + 64);  // 16 ints

    int tid  = threadIdx.x;
    int lane = tid & 31;
    int warp = tid >> 5;
    float a4 = a4p[0];

    #pragma unroll
    for (int i = tid; i < 2 * NC * 128; i += 256) s_acc[i] = 0ull;
    if (tid < NC) s_cnt[tid] = 0;

    float wp0 = wwp[0], wp1 = wwp[1], wp2 = wwp[2];
    float f0 = wwf[0], f1 = wwf[1];
    float4 cA, cB;
    {
        float4 q1 = p14[lane], q2 = p24[lane], q3 = p34[lane], qd = wdp4[lane];
        float s;
        s = wp0*q1.x + wp1*q2.x + wp2*q3.x; cA.x = f0*(s > 0.f ? s+1.f : __expf(s)) + f1*qd.x;
        s = wp0*q1.y + wp1*q2.y + wp2*q3.y; cA.y = f0*(s > 0.f ? s+1.f : __expf(s)) + f1*qd.y;
        s = wp0*q1.z + wp1*q2.z + wp2*q3.z; cA.z = f0*(s > 0.f ? s+1.f : __expf(s)) + f1*qd.z;
        s = wp0*q1.w + wp1*q2.w + wp2*q3.w; cA.w = f0*(s > 0.f ? s+1.f : __expf(s)) + f1*qd.w;
        q1 = p14[lane+32]; q2 = p24[lane+32]; q3 = p34[lane+32]; qd = wdp4[lane+32];
        s = wp0*q1.x + wp1*q2.x + wp2*q3.x; cB.x = f0*(s > 0.f ? s+1.f : __expf(s)) + f1*qd.x;
        s = wp0*q1.y + wp1*q2.y + wp2*q3.y; cB.y = f0*(s > 0.f ? s+1.f : __expf(s)) + f1*qd.y;
        s = wp0*q1.z + wp1*q2.z + wp2*q3.z; cB.z = f0*(s > 0.f ? s+1.f : __expf(s)) + f1*qd.z;
        s = wp0*q1.w + wp1*q2.w + wp2*q3.w; cB.w = f0*(s > 0.f ? s+1.f : __expf(s)) + f1*qd.w;
    }
    __syncthreads();

    for (int tile = blockIdx.x; tile < ntiles; tile += gridDim.x) {
        int base = tile * TILE_ROWS;
        if (tid < 16) {
            int lb = labels[base + tid];
            s_lab[tid] = lb;
            // deterministic, atomic-free histogram: one leader lane per class
            unsigned m = __match_any_sync(0x0000FFFFu, lb);
            if ((int)(__ffs(m) - 1) == tid) s_cnt[lb] += __popc(m);
        }

        // ---- phase A: pointwise, row norms, fp16 pack -> smem + global row-major ----
        #pragma unroll
        for (int q = 0; q < 2; q++) {
            int rloc = warp * 2 + q;
            size_t row = (size_t)base + rloc;
            float4 xa = seq4 [row * 64 + lane];
            float4 xb = seq4 [row * 64 + 32 + lane];
            float4 ya = seq14[row * 64 + lane];
            float4 yb = seq14[row * 64 + 32 + lane];
            float4 ra, rb;
            ra.x = fmaf(a4, ya.x, eluf(cA.x * xa.x));
            ra.y = fmaf(a4, ya.y, eluf(cA.y * xa.y));
            ra.z = fmaf(a4, ya.z, eluf(cA.z * xa.z));
            ra.w = fmaf(a4, ya.w, eluf(cA.w * xa.w));
            rb.x = fmaf(a4, yb.x, eluf(cB.x * xb.x));
            rb.y = fmaf(a4, yb.y, eluf(cB.y * xb.y));
            rb.z = fmaf(a4, yb.z, eluf(cB.z * xb.z));
            rb.w = fmaf(a4, yb.w, eluf(cB.w * xb.w));
            float ss = ra.x*ra.x + ra.y*ra.y + ra.z*ra.z + ra.w*ra.w
                     + rb.x*rb.x + rb.y*rb.y + rb.z*rb.z + rb.w*rb.w;
            #pragma unroll
            for (int o = 16; o; o >>= 1) ss += __shfl_xor_sync(0xffffffffu, ss, o);
            if (lane == 0) g_rnorm[row] = sqrtf(ss);

            __half2 h0 = __floats2half2_rn(ra.x, ra.y);
            __half2 h1 = __floats2half2_rn(ra.z, ra.w);
            __half2 h2 = __floats2half2_rn(rb.x, rb.y);
            __half2 h3 = __floats2half2_rn(rb.z, rb.w);
            uint2 w0; w0.x = *(uint32_t*)&h0; w0.y = *(uint32_t*)&h1;
            uint2 w1; w1.x = *(uint32_t*)&h2; w1.y = *(uint32_t*)&h3;
            *(uint2*)(s_tile + rloc * 128 + 2 * lane)      = w0;
            *(uint2*)(s_tile + rloc * 128 + 64 + 2 * lane) = w1;
            ((uint2*)(g_rawH + row * FT))[lane]      = w0;
            ((uint2*)(g_rawH + row * FT))[32 + lane] = w1;
        }
        __syncthreads();

        // ---- phase B: class partial sums (thread = (colpair, rowgroup of 8), exclusive) ----
        {
            int c2 = tid & 127;
            int rg = tid >> 7;
            ull* accb = s_acc + (size_t)rg * NC * 128 + c2;
            #pragma unroll
            for (int rr = 0; rr < 8; rr++) {
                int r = rg * 8 + rr;
                int lab = s_lab[r];
                __half2 h = s_tile[r * 128 + c2];
                float2 f = __half22float2(h);
                ull v = pack2(f.x, f.y);
                ull* a = accb + lab * 128;
                ull old = *a;
                asm("add.rn.f32x2 %0, %0, %1;" : "+l"(old) : "l"(v));
                *a = old;
            }
        }
        __syncthreads();
    }

    {
        ull* gp = (ull*)g_partial + (size_t)blockIdx.x * (NC * 128);
        #pragma unroll
        for (int i = tid; i < NC * 128; i += 256) {
            ull a = s_acc[i], b = s_acc[NC * 128 + i];
            asm("add.rn.f32x2 %0, %0, %1;" : "+l"(a) : "l"(b));
            gp[i] = a;
        }
        if (tid < NC) g_pcnt[blockIdx.x * NC + tid] = s_cnt[tid];
    }
}

// ============ kernel 2: reduce partials -> ave (fp16 B image), avenorm ============
__global__ void __launch_bounds__(1024)
k_reduce() {
    __shared__ float s_part[3 * 256];
    __shared__ float s_ave2[256];
    __shared__ float s_red[8];
    __shared__ int   s_ci[32];
    __shared__ int   s_cnt;
    int cls = blockIdx.x, tid = threadIdx.x;
    int col = tid & 255, grp = tid >> 8;

    // 4-way split partial sum (148 blocks each; 592 = 4*148)
    float s = 0.f;
    const float* gp = g_partial + (size_t)cls * 256 + col + (size_t)(grp * 148) * 4096;
    #pragma unroll 4
    for (int b = 0; b < 148; b++) s += gp[(size_t)b * 4096];
    if (grp) s_part[(grp - 1) * 256 + col] = s;

    // class count from per-block integer histograms
    int c = (tid < G2) ? g_pcnt[tid * NC + cls] : 0;
    #pragma unroll
    for (int o = 16; o; o >>= 1) c += __shfl_xor_sync(0xffffffffu, c, o);
    if ((tid & 31) == 0) s_ci[tid >> 5] = c;
    __syncthreads();
    if (tid == 0) {
        int t = 0;
        #pragma unroll
        for (int i = 0; i < 32; i++) t += s_ci[i];
        s_cnt = t;
    }
    __syncthreads();

    if (grp == 0) {
        float a = (s + s_part[col] + s_part[256 + col] + s_part[512 + col])
                / fmaxf((float)s_cnt, 1.f);
        __half hv = __float2half_rn(a);
        float af = __half2float(hv);
        s_ave2[col] = af * af;
        // swizzled B image: row=cls (512B rows), 16B-chunk index XOR (cls&7)
        int chunk = col >> 3;
        int off = cls * 512 + ((chunk ^ (cls & 7)) << 4) + (col & 7) * 2;
        *(__half*)((char*)g_aveH + off) = hv;
    }
    __syncthreads();

    if (tid < 256) {
        float v = s_ave2[tid];
        #pragma unroll
        for (int o = 16; o; o >>= 1) v += __shfl_xor_sync(0xffffffffu, v, o);
        if ((tid & 31) == 0) s_red[tid >> 5] = v;
    }
    __syncthreads();
    if (tid == 0) {
        float t = 0.f;
        #pragma unroll
        for (int i = 0; i < 8; i++) t += s_red[i];
        g_avenorm[cls] = sqrtf(t);
    }
}

// ============ kernel 3: HMMA GEMM + cosine + softmax; warp-per-16-rows ============
// smem: A 64KB (8 warp slices x 8KB, chunk^row swizzle) + B 8KB (pre-swizzled)
__global__ void __launch_bounds__(256)
k_out(float* __restrict__ out, int N) {
    extern __shared__ char sm[];
    uint32_t sA = smem_u32(sm);
    uint32_t sB = sA + 65536u;

    int tid  = threadIdx.x;
    int wid  = tid >> 5;
    int lane = tid & 31;
    int rowbase = blockIdx.x * MTILE + wid * 16;

    // B image: 512 chunks, 2 per thread
    {
        const char* gB = (const char*)g_aveH;
        #pragma unroll
        for (int it = 0; it < 2; it++) {
            int i = it * 256 + tid;
            asm volatile("cp.async.cg.shared.global [%0], [%1], 16;"
                         :: "r"(sB + i * 16), "l"(gB + (size_t)i * 16) : "memory");
        }
    }
    // A warp slice: 16 rows x 512B
    {
        const char* gA = (const char*)(g_rawH + (size_t)rowbase * FT);
        uint32_t aslice = sA + (uint32_t)(wid * 8192);
        #pragma unroll
        for (int it = 0; it < 16; it++) {
            uint32_t off = aslice + (uint32_t)(it * 512) + (uint32_t)((lane ^ (it & 7)) << 4);
            asm volatile("cp.async.cg.shared.global [%0], [%1], 16;"
                         :: "r"(off), "l"(gA + (size_t)it * 512 + (size_t)lane * 16) : "memory");
        }
    }
    asm volatile("cp.async.commit_group;" ::: "memory");
    asm volatile("cp.async.wait_group 0;" ::: "memory");
    __syncthreads();

    // ---- mma.sync m16n8k16: one m16 tile per warp, 2 n-tiles, 16 k-steps ----
    float c0[4] = {0,0,0,0}, c1[4] = {0,0,0,0};
    int sel   = lane >> 3;
    int lrow8 = lane & 7;
    int lrA = (sel & 1) * 8 + lrow8;     // local A row 0..15
    int cAadd = sel >> 1;
    int rB  = (sel >> 1) * 8 + lrow8;    // B row (class)
    int cBadd = sel & 1;
    uint32_t aab = sA + (uint32_t)(wid * 8192) + (uint32_t)(lrA * 512);
    uint32_t bab = sB + (uint32_t)(rB * 512);

    #pragma unroll
    for (int k = 0; k < 16; k++) {
        int cbase = 2 * k;
        uint32_t b0, b1, b2, b3;
        uint32_t baddr = bab + (uint32_t)(((cbase + cBadd) ^ (rB & 7)) << 4);
        asm volatile("ldmatrix.sync.aligned.m8n8.x4.shared.b16 {%0,%1,%2,%3}, [%4];"
                     : "=r"(b0), "=r"(b1), "=r"(b2), "=r"(b3) : "r"(baddr));
        uint32_t a0, a1, a2, a3;
        uint32_t aaddr = aab + (uint32_t)(((cbase + cAadd) ^ (lrA & 7)) << 4);
        asm volatile("ldmatrix.sync.aligned.m8n8.x4.shared.b16 {%0,%1,%2,%3}, [%4];"
                     : "=r"(a0), "=r"(a1), "=r"(a2), "=r"(a3) : "r"(aaddr));
        asm volatile("mma.sync.aligned.m16n8k16.row.col.f32.f16.f16.f32 "
                     "{%0,%1,%2,%3}, {%4,%5,%6,%7}, {%8,%9}, {%0,%1,%2,%3};"
                     : "+f"(c0[0]), "+f"(c0[1]), "+f"(c0[2]), "+f"(c0[3])
                     : "r"(a0), "r"(a1), "r"(a2), "r"(a3), "r"(b0), "r"(b1));
        asm volatile("mma.sync.aligned.m16n8k16.row.col.f32.f16.f16.f32 "
                     "{%0,%1,%2,%3}, {%4,%5,%6,%7}, {%8,%9}, {%0,%1,%2,%3};"
                     : "+f"(c1[0]), "+f"(c1[1]), "+f"(c1[2]), "+f"(c1[3])
                     : "r"(a0), "r"(a1), "r"(a2), "r"(a3), "r"(b2), "r"(b3));
    }

    // ---- epilogue: quad owns a row's 16 cols; cosine + softmax in registers ----
    int j2 = (lane & 3) * 2;
    float an0 = __ldg(&g_avenorm[j2]);
    float an1 = __ldg(&g_avenorm[j2 + 1]);
    float an2 = __ldg(&g_avenorm[j2 + 8]);
    float an3 = __ldg(&g_avenorm[j2 + 9]);

    #pragma unroll
    for (int h = 0; h < 2; h++) {
        int r = rowbase + (lane >> 2) + h * 8;
        int rc = r < N ? r : N - 1;
        float rn = __ldg(&g_rnorm[rc]);
        float v0 = __fdividef(c0[2*h],   fmaxf(rn * an0, 1e-8f));
        float v1 = __fdividef(c0[2*h+1], fmaxf(rn * an1, 1e-8f));
        float v2 = __fdividef(c1[2*h],   fmaxf(rn * an2, 1e-8f));
        float v3 = __fdividef(c1[2*h+1], fmaxf(rn * an3, 1e-8f));
        float mx = fmaxf(fmaxf(v0, v1), fmaxf(v2, v3));
        mx = fmaxf(mx, __shfl_xor_sync(0xffffffffu, mx, 1));
        mx = fmaxf(mx, __shfl_xor_sync(0xffffffffu, mx, 2));
        v0 = __expf(v0 - mx); v1 = __expf(v1 - mx);
        v2 = __expf(v2 - mx); v3 = __expf(v3 - mx);
        float ssum = v0 + v1 + v2 + v3;
        ssum += __shfl_xor_sync(0xffffffffu, ssum, 1);
        ssum += __shfl_xor_sync(0xffffffffu, ssum, 2);
        float inv = 1.f / ssum;
        if (r < N) {
            float2* op = (float2*)(out + (size_t)r * NC);
            op[j2 >> 1]       = make_float2(v0 * inv, v1 * inv);
            op[(j2 >> 1) + 4] = make_float2(v2 * inv, v3 * inv);
        }
    }
}

// ---------------- launcher ----------------
extern "C" void kernel_launch(void* const* d_in, const int* in_sizes, int n_in,
                              void* d_out, int out_size) {
    const float* seq    = (const float*)d_in[0];
    const float* seq1   = (const float*)d_in[1];
    const int*   labels = (const int*)  d_in[2];
    const float* p1     = (const float*)d_in[3];
    const float* p2     = (const float*)d_in[4];
    const float* p3     = (const float*)d_in[5];
    const float* wwp    = (const float*)d_in[6];
    const float* wwf    = (const float*)d_in[7];
    const float* wdp    = (const float*)d_in[8];
    const float* a4     = (const float*)d_in[9];
    float* out = (float*)d_out;

    int N = in_sizes[0] / FT;
    if (N > NMAX) N = NMAX;
    int ntiles = N / TILE_ROWS;                 // 100000 = 6250 * 16 exactly
    int mtiles = (N + MTILE - 1) / MTILE;       // 782

    int smem1 = 8192 + 32768 + 64 + 64;         // tile + acc + labels + counters
    int smem3 = 65536 + 8192;                   // 72KB
    cudaFuncSetAttribute(k_main, cudaFuncAttributeMaxDynamicSharedMemorySize, smem1);
    cudaFuncSetAttribute(k_out,  cudaFuncAttributeMaxDynamicSharedMemorySize, smem3);

    k_main<<<G2, 256, smem1>>>((const float4*)seq, (const float4*)seq1, labels,
                               (const float4*)p1, (const float4*)p2, (const float4*)p3,
                               wwp, wwf, (const float4*)wdp, a4, N, ntiles);
    k_reduce<<<NC, 1024>>>();
    k_out<<<mtiles, 256, smem3>>>(out, N);
}